// round 7
// baseline (speedup 1.0000x reference)
#include <cuda_runtime.h>
#include <math.h>

#define N_NODES 100000
#define N_EDGES 600000
#define D 128
#define ROWS 32           // nodes per block in the GEMM kernel (100000/32 = 3125 exact)
#define SW_STRIDE 132     // floats; 528B row stride: 16B-aligned, conflict-free LDS.128

// Scratch (no allocation allowed anywhere): scatter accumulator + per-node counts.
__device__ float g_acc[(size_t)N_NODES * D];
__device__ float g_cnt[N_NODES];

// ---------------------------------------------------------------------------
// Edge scatter: one warp per edge. Each lane handles one float4 (4 dims).
// acc[src] += |x[src] - x[dst]| via a single vector reduction (sm_90+):
//   red.global.add.v4.f32  — 1 instruction instead of 4 scalar REDG.
// cnt[src] += 1 (lane 0 only).
// ---------------------------------------------------------------------------
__global__ void __launch_bounds__(256, 8)
edge_kernel(const float4* __restrict__ x4,
            const int* __restrict__ src,
            const int* __restrict__ dst,
            float* __restrict__ acc,
            float* __restrict__ cnt) {
    int gtid = blockIdx.x * blockDim.x + threadIdx.x;
    int e    = gtid >> 5;
    int lane = gtid & 31;
    if (e >= N_EDGES) return;

    int s = src[e];
    int d = dst[e];

    float4 a = x4[(size_t)s * 32 + lane];
    float4 b = x4[(size_t)d * 32 + lane];

    float m0 = fabsf(a.x - b.x);
    float m1 = fabsf(a.y - b.y);
    float m2 = fabsf(a.z - b.z);
    float m3 = fabsf(a.w - b.w);

    float* p = acc + (size_t)s * D + lane * 4;   // 16B-aligned
    asm volatile("red.global.add.v4.f32 [%0], {%1, %2, %3, %4};"
                 :: "l"(p), "f"(m0), "f"(m1), "f"(m2), "f"(m3)
                 : "memory");

    if (lane == 0) atomicAdd(cnt + s, 1.0f);
}

// ---------------------------------------------------------------------------
// Output: out[n][j] = dot( (x[n]+acc[n]) / (cnt[n]+1), W[j][:] ) + b[j]
// Block: 128 threads (one per output column j), ROWS=32 nodes per block.
// W staged in shared at stride 132 floats (528B): conflict-free fill (16B
// aligned STS.128) and read (per-8-lane-phase LDS.128 spans all banks).
// k-loop: per k4, 1 w-LDS.128 + ROWS broadcast sn-LDS.128 + 4*ROWS FFMA
// => FFMA-issue-bound. Unroll limited to 4 to keep SASS body ~10KB (I$-safe).
// ---------------------------------------------------------------------------
__global__ void __launch_bounds__(128, 2)
out_kernel(const float* __restrict__ x,
           const float* __restrict__ W,
           const float* __restrict__ bias,
           const float* __restrict__ acc,
           const float* __restrict__ cnt,
           float* __restrict__ out) {
    extern __shared__ float sm[];
    float* sW = sm;                       // 128 * SW_STRIDE floats
    float* sn = sm + 128 * SW_STRIDE;     // ROWS * 128 floats

    const int j = threadIdx.x;            // 0..127

    // Stage W: 4096 float4s total, 32 per thread.
    const float4* W4 = reinterpret_cast<const float4*>(W);
    #pragma unroll
    for (int i = 0; i < 32; i++) {
        int q   = i * 128 + j;            // float4 index into W
        int row = q >> 5;
        int c4  = q & 31;
        *reinterpret_cast<float4*>(sW + row * SW_STRIDE + c4 * 4) = W4[q];
    }

    // Stage normalized node rows: sn[r][k] = (x + acc) / (cnt + 1)
    // Vectorized: ROWS*32 = 1024 float4s, 8 per thread.
    const int n0 = blockIdx.x * ROWS;
    const float4* x4v   = reinterpret_cast<const float4*>(x + (size_t)n0 * D);
    const float4* acc4v = reinterpret_cast<const float4*>(acc + (size_t)n0 * D);
    #pragma unroll
    for (int i = 0; i < ROWS * 32 / 128; i++) {   // 8 iterations
        int q  = i * 128 + j;                     // float4 index in block tile
        int r  = q >> 5;                          // row 0..ROWS-1
        float inv = 1.0f / (cnt[n0 + r] + 1.0f);  // broadcast load per 32-lane group
        float4 xv = x4v[q];
        float4 av = acc4v[q];
        float4 o;
        o.x = (xv.x + av.x) * inv;
        o.y = (xv.y + av.y) * inv;
        o.z = (xv.z + av.z) * inv;
        o.w = (xv.w + av.w) * inv;
        *reinterpret_cast<float4*>(sn + q * 4) = o;
    }
    __syncthreads();

    float accum[ROWS];
    #pragma unroll
    for (int r = 0; r < ROWS; r++) accum[r] = 0.0f;

    // k4 loop: unroll 4 (not full) to keep the SASS body inside the I$.
    #pragma unroll 4
    for (int k4 = 0; k4 < 32; k4++) {
        float4 w = *reinterpret_cast<const float4*>(sW + j * SW_STRIDE + k4 * 4);
        #pragma unroll
        for (int r = 0; r < ROWS; r++) {
            float4 s = *reinterpret_cast<const float4*>(sn + r * 128 + k4 * 4);
            accum[r] += w.x * s.x;
            accum[r] += w.y * s.y;
            accum[r] += w.z * s.z;
            accum[r] += w.w * s.w;
        }
    }

    float bj = bias[j];
    #pragma unroll
    for (int r = 0; r < ROWS; r++) {
        out[(size_t)(n0 + r) * D + j] = accum[r] + bj;
    }
}

// ---------------------------------------------------------------------------
// Launch: memset scratch -> edge scatter -> fused normalize+GEMM.
// Default stream only; graph-capturable (memset nodes + kernel nodes).
// ---------------------------------------------------------------------------
extern "C" void kernel_launch(void* const* d_in, const int* in_sizes, int n_in,
                              void* d_out, int out_size) {
    const float* x  = (const float*)d_in[0];                 // [N, 128]
    const int*   ei = (const int*)d_in[1];                   // [2, E]
    const float* W  = (const float*)d_in[2];                 // [128, 128]
    const float* b  = (const float*)d_in[3];                 // [128]
    float* out      = (float*)d_out;

    const int* src = ei;
    const int* dst = ei + N_EDGES;

    void* accPtr = nullptr;
    void* cntPtr = nullptr;
    cudaGetSymbolAddress(&accPtr, g_acc);
    cudaGetSymbolAddress(&cntPtr, g_cnt);

    cudaMemsetAsync(accPtr, 0, (size_t)N_NODES * D * sizeof(float));
    cudaMemsetAsync(cntPtr, 0, (size_t)N_NODES * sizeof(float));

    // Edge scatter: 1 warp per edge, 256 threads per block = 8 edges/block.
    {
        int threads = 256;
        int blocks  = (N_EDGES * 32 + threads - 1) / threads;
        edge_kernel<<<blocks, threads>>>(
            (const float4*)x, src, dst, (float*)accPtr, (float*)cntPtr);
    }

    // Output GEMM: 3125 blocks x 128 threads, 32 rows each.
    {
        size_t smem = (128 * SW_STRIDE + ROWS * 128) * sizeof(float);
        cudaFuncSetAttribute(out_kernel,
                             cudaFuncAttributeMaxDynamicSharedMemorySize,
                             (int)smem);
        int blocks = N_NODES / ROWS;   // 100000 / 32 = 3125, exact
        out_kernel<<<blocks, 128, smem>>>(
            x, W, b, (const float*)accPtr, (const float*)cntPtr, out);
    }
}

// round 8
// speedup vs baseline: 1.2721x; 1.2721x over previous
#include <cuda_runtime.h>
#include <math.h>

#define N_NODES 100000
#define N_EDGES 600000
#define D 128
#define ROWS 32                      // nodes per tile
#define STRIDE 132                   // smem row stride in floats (528B): 16B-aligned, banks 4jj
#define NTILES (N_NODES / ROWS)      // 3125
#define GRID_OUT 296                 // persistent: 2 CTAs per SM on 148 SMs

// Scratch (no allocation allowed anywhere): scatter accumulator + per-node counts.
__device__ float g_acc[(size_t)N_NODES * D];
__device__ float g_cnt[N_NODES];

// ---------------------------------------------------------------------------
// Edge scatter: one warp per edge, lane = one float4 of the 128-dim row.
// acc[src] += |x[src]-x[dst]| via red.global.add.v4.f32; cnt[src] += 1.
// ---------------------------------------------------------------------------
__global__ void __launch_bounds__(256, 8)
edge_kernel(const float4* __restrict__ x4,
            const int* __restrict__ src,
            const int* __restrict__ dst,
            float* __restrict__ acc,
            float* __restrict__ cnt) {
    int gtid = blockIdx.x * blockDim.x + threadIdx.x;
    int e    = gtid >> 5;
    int lane = gtid & 31;
    if (e >= N_EDGES) return;

    int s = src[e];
    int d = dst[e];

    float4 a = x4[(size_t)s * 32 + lane];
    float4 b = x4[(size_t)d * 32 + lane];

    float m0 = fabsf(a.x - b.x);
    float m1 = fabsf(a.y - b.y);
    float m2 = fabsf(a.z - b.z);
    float m3 = fabsf(a.w - b.w);

    float* p = acc + (size_t)s * D + lane * 4;
    asm volatile("red.global.add.v4.f32 [%0], {%1, %2, %3, %4};"
                 :: "l"(p), "f"(m0), "f"(m1), "f"(m2), "f"(m3)
                 : "memory");

    if (lane == 0) atomicAdd(cnt + s, 1.0f);
}

// Packed dual-FMA: d.lo += a.lo*b.lo, d.hi += a.hi*b.hi  (sm_103a f32x2 pipe)
__device__ __forceinline__ void fma2(unsigned long long& d,
                                     unsigned long long a,
                                     unsigned long long b) {
    asm("fma.rn.f32x2 %0, %1, %2, %0;" : "+l"(d) : "l"(a), "l"(b));
}

// ---------------------------------------------------------------------------
// Persistent fused normalize+GEMM.
//   out[n][j] = dot((x[n]+acc[n])/(cnt[n]+1), W[j][:]) + b[j]
// 296 blocks x 256 threads; W staged in smem ONCE per block; node tiles of 32
// rows processed with ping-pong sn buffers (1 syncthreads per tile, staging
// overlapped with compute). Thread tile 4j x 4r, k-pair-packed fma.rn.f32x2:
// per k4 per thread: 4 w-LDS.128 + 4 s-LDS.128 + 32 packed FMAs.
// Lane map: jj=lane&7, rr=lane>>3; js = j0+jj+8c (stride-132 rows -> banks
// 4jj+{0..3}, conflict-free); rs = r0+rr+4c (phase-uniform broadcast).
// ---------------------------------------------------------------------------
__global__ void __launch_bounds__(256, 2)
out_kernel(const float* __restrict__ x,
           const float* __restrict__ W,
           const float* __restrict__ bias,
           const float* __restrict__ acc,
           const float* __restrict__ cnt,
           float* __restrict__ out) {
    extern __shared__ float sm[];
    float* sW  = sm;                          // 128 * STRIDE floats
    float* sn0 = sm + 128 * STRIDE;           // 2 buffers of ROWS * STRIDE

    const int tid  = threadIdx.x;
    const int lane = tid & 31;
    const int warp = tid >> 5;
    const int jj   = lane & 7;
    const int rr   = lane >> 3;
    const int j0   = (warp & 3) * 32;
    const int r0   = (warp >> 2) * 16;

    // ---- Stage W once: 4096 float4s, 16 per thread (conflict-free STS.128).
    const float4* W4 = reinterpret_cast<const float4*>(W);
    #pragma unroll
    for (int i = 0; i < 16; i++) {
        int q   = i * 256 + tid;
        int row = q >> 5;
        int c4  = q & 31;
        *reinterpret_cast<float4*>(sW + row * STRIDE + c4 * 4) = W4[q];
    }

    // ---- Preload this thread's 4 bias values.
    float bj[4];
    #pragma unroll
    for (int c = 0; c < 4; c++) bj[c] = bias[j0 + jj + 8 * c];

    int t = blockIdx.x;

    // ---- Stage first sn tile into buffer 0.
    {
        int n0 = t * ROWS;
        const float4* xv = reinterpret_cast<const float4*>(x   + (size_t)n0 * D);
        const float4* av = reinterpret_cast<const float4*>(acc + (size_t)n0 * D);
        #pragma unroll
        for (int i = 0; i < 4; i++) {
            int q = i * 256 + tid;
            int r = q >> 5;
            int c4 = q & 31;
            float inv = 1.0f / (cnt[n0 + r] + 1.0f);
            float4 a = xv[q], b = av[q];
            float4 o;
            o.x = (a.x + b.x) * inv; o.y = (a.y + b.y) * inv;
            o.z = (a.z + b.z) * inv; o.w = (a.w + b.w) * inv;
            *reinterpret_cast<float4*>(sn0 + r * STRIDE + c4 * 4) = o;
        }
    }
    __syncthreads();

    int buf = 0;
    for (; t < NTILES; t += GRID_OUT) {
        // ---- Stage NEXT tile into the other buffer (overlaps with compute).
        int tn = t + GRID_OUT;
        if (tn < NTILES) {
            float* bufp = sn0 + (buf ^ 1) * ROWS * STRIDE;
            int n0 = tn * ROWS;
            const float4* xv = reinterpret_cast<const float4*>(x   + (size_t)n0 * D);
            const float4* av = reinterpret_cast<const float4*>(acc + (size_t)n0 * D);
            #pragma unroll
            for (int i = 0; i < 4; i++) {
                int q = i * 256 + tid;
                int r = q >> 5;
                int c4 = q & 31;
                float inv = 1.0f / (cnt[n0 + r] + 1.0f);
                float4 a = xv[q], b = av[q];
                float4 o;
                o.x = (a.x + b.x) * inv; o.y = (a.y + b.y) * inv;
                o.z = (a.z + b.z) * inv; o.w = (a.w + b.w) * inv;
                *reinterpret_cast<float4*>(bufp + r * STRIDE + c4 * 4) = o;
            }
        }

        // ---- Compute tile t from current buffer.
        const float* snb = sn0 + buf * ROWS * STRIDE;

        unsigned long long a2[4][4];
        #pragma unroll
        for (int jc = 0; jc < 4; jc++)
            #pragma unroll
            for (int rc = 0; rc < 4; rc++) a2[jc][rc] = 0ull;

        #pragma unroll 4
        for (int k4 = 0; k4 < 32; k4++) {
            unsigned long long wf[4][2], sf[4][2];
            #pragma unroll
            for (int c = 0; c < 4; c++) {
                ulonglong2 v = *reinterpret_cast<const ulonglong2*>(
                    sW + (j0 + jj + 8 * c) * STRIDE + k4 * 4);
                wf[c][0] = v.x; wf[c][1] = v.y;
            }
            #pragma unroll
            for (int c = 0; c < 4; c++) {
                ulonglong2 v = *reinterpret_cast<const ulonglong2*>(
                    snb + (r0 + rr + 4 * c) * STRIDE + k4 * 4);
                sf[c][0] = v.x; sf[c][1] = v.y;
            }
            #pragma unroll
            for (int jc = 0; jc < 4; jc++)
                #pragma unroll
                for (int rc = 0; rc < 4; rc++) {
                    fma2(a2[jc][rc], wf[jc][0], sf[rc][0]);
                    fma2(a2[jc][rc], wf[jc][1], sf[rc][1]);
                }
        }

        // ---- Epilogue: lo+hi reduce, bias, store.
        int n0 = t * ROWS;
        #pragma unroll
        for (int jc = 0; jc < 4; jc++) {
            int j = j0 + jj + 8 * jc;
            #pragma unroll
            for (int rc = 0; rc < 4; rc++) {
                int r = r0 + rr + 4 * rc;
                uint2 u = *reinterpret_cast<uint2*>(&a2[jc][rc]);
                float v = __uint_as_float(u.x) + __uint_as_float(u.y) + bj[jc];
                out[(size_t)(n0 + r) * D + j] = v;
            }
        }

        __syncthreads();     // staging(next) done AND compute(t) done
        buf ^= 1;
    }
}

// ---------------------------------------------------------------------------
// Launch: memset scratch -> edge scatter -> persistent normalize+GEMM.
// Default stream only; graph-capturable.
// ---------------------------------------------------------------------------
extern "C" void kernel_launch(void* const* d_in, const int* in_sizes, int n_in,
                              void* d_out, int out_size) {
    const float* x  = (const float*)d_in[0];                 // [N, 128]
    const int*   ei = (const int*)d_in[1];                   // [2, E]
    const float* W  = (const float*)d_in[2];                 // [128, 128]
    const float* b  = (const float*)d_in[3];                 // [128]
    float* out      = (float*)d_out;

    const int* src = ei;
    const int* dst = ei + N_EDGES;

    void* accPtr = nullptr;
    void* cntPtr = nullptr;
    cudaGetSymbolAddress(&accPtr, g_acc);
    cudaGetSymbolAddress(&cntPtr, g_cnt);

    cudaMemsetAsync(accPtr, 0, (size_t)N_NODES * D * sizeof(float));
    cudaMemsetAsync(cntPtr, 0, (size_t)N_NODES * sizeof(float));

    // Edge scatter: 1 warp per edge.
    {
        int threads = 256;
        int blocks  = (N_EDGES * 32 + threads - 1) / threads;
        edge_kernel<<<blocks, threads>>>(
            (const float4*)x, src, dst, (float*)accPtr, (float*)cntPtr);
    }

    // Persistent output GEMM.
    {
        size_t smem = (128 * STRIDE + 2 * ROWS * STRIDE) * sizeof(float); // 101,376B
        cudaFuncSetAttribute(out_kernel,
                             cudaFuncAttributeMaxDynamicSharedMemorySize,
                             (int)smem);
        out_kernel<<<GRID_OUT, 256, smem>>>(
            x, W, b, (const float*)accPtr, (const float*)cntPtr, out);
    }
}